// round 9
// baseline (speedup 1.0000x reference)
#include <cuda_runtime.h>
#include <cuda_bf16.h>
#include <math.h>
#include <cstdint>

// Problem constants
#define Bb 4
#define Tt 1024
#define Cc 1024
#define Hh 16
#define HKV 4
#define Dd 64
#define ROWS (Bb*Tt)          // 4096 tokens
#define QDIM (Hh*Dd)          // 1024
#define KVDIM (HKV*Dd)        // 256
#define GATE_CH 12

#define XN  (ROWS * Cc)       // 4194304
#define WQN (QDIM * Cc)       // 1048576
#define WKN (KVDIM * Cc)      // 262144
#define WON (Cc * Cc)         // 1048576

// Scratch (no cudaMalloc allowed)
__device__ float g_Q[ROWS * QDIM];    // 16 MB
__device__ float g_K[ROWS * KVDIM];   // 4 MB
__device__ float g_V[ROWS * KVDIM];   // 4 MB
__device__ float g_Y[ROWS * QDIM];    // 16 MB (k-permuted layout)
__device__ float g_Xr[XN];            // 16 MB  tf32-rounded, k-permuted
__device__ float g_Wqr[WQN];          // 4 MB
__device__ float g_Wkr[WKN];          // 1 MB
__device__ float g_Wvr[WKN];          // 1 MB
__device__ float g_Wor[WON];          // 4 MB

// k-block permutation: within each 32-col block, col j stored at perm(j)
__device__ __forceinline__ int permc(int j) { return ((j & 3) << 3) | (j >> 2); }
__device__ __forceinline__ int invpc(int p) { return ((p & 7) << 2) | (p >> 3); }

__device__ __forceinline__ float tf32r(float x) {
    float y;
    asm("cvt.rna.tf32.f32 %0, %1;" : "=f"(y) : "f"(x));
    return y;
}

__device__ __forceinline__ void mma_tf32(float* d,
                                         const uint32_t* a, const uint32_t* b) {
    asm volatile(
        "mma.sync.aligned.m16n8k8.row.col.f32.tf32.tf32.f32 "
        "{%0,%1,%2,%3}, {%4,%5,%6,%7}, {%8,%9}, {%0,%1,%2,%3};"
        : "+f"(d[0]), "+f"(d[1]), "+f"(d[2]), "+f"(d[3])
        : "r"(a[0]), "r"(a[1]), "r"(a[2]), "r"(a[3]),
          "r"(b[0]), "r"(b[1]));
}

__device__ __forceinline__ void cpa16(float* s, const float* g) {
    uint32_t sa = (uint32_t)__cvta_generic_to_shared(s);
    asm volatile("cp.async.cg.shared.global [%0], [%1], 16;"
                 :: "r"(sa), "l"(g) : "memory");
}

// ---------------------------------------------------------------------------
// Pre-round + permute pass: tf32-round x and weights into k-permuted layout.
// Each thread gathers 4 source elements and writes one dst float4.
// ---------------------------------------------------------------------------
#define RND_TOTAL4 ((XN + WQN + 2 * WKN + WON) / 4)

__global__ __launch_bounds__(256) void round_pass(
    const float* __restrict__ x,
    const float* __restrict__ Wq, const float* __restrict__ Wk,
    const float* __restrict__ Wv, const float* __restrict__ Wo)
{
    int id = blockIdx.x * 256 + threadIdx.x;
    if (id >= RND_TOTAL4) return;
    int e = id * 4;                       // dst element offset (matrix-local after cascade)
    const float* sb;
    float* db;
    if (e < XN)                { sb = x;  db = g_Xr;  }
    else if ((e -= XN) < WQN)  { sb = Wq; db = g_Wqr; }
    else if ((e -= WQN) < WKN) { sb = Wk; db = g_Wkr; }
    else if ((e -= WKN) < WKN) { sb = Wv; db = g_Wvr; }
    else                       { e -= WKN; sb = Wo; db = g_Wor; }

    int rowbase = e & ~1023;              // K = 1024 for every matrix
    int col = e & 1023;
    int blk = rowbase + (col & ~31);
    int p = col & 31;                     // dst position within block (4-aligned)
    float4 v;
    v.x = tf32r(sb[blk + invpc(p + 0)]);
    v.y = tf32r(sb[blk + invpc(p + 1)]);
    v.z = tf32r(sb[blk + invpc(p + 2)]);
    v.w = tf32r(sb[blk + invpc(p + 3)]);
    *(float4*)(db + e) = v;
}

// ---------------------------------------------------------------------------
// tf32 mma.sync GEMM core:  C_tile = A[128,K] * B[128,K]^T
// Operands pre-rounded AND k-permuted -> LDS.128 fragment loads.
// ---------------------------------------------------------------------------
#define LDS_S 36
#define STG (128 * LDS_S)

__device__ __forceinline__ void gemm_body(
    const float* __restrict__ Ab, const float* __restrict__ Bp,
    float* __restrict__ Crow0, int N, int K, float* __restrict__ sm)
{
    float* smA = sm;
    float* smB = sm + 2 * STG;

    const int tid = threadIdx.x;
    const int wid = tid >> 5;
    const int lane = tid & 31;
    const int warp_m = wid & 3;
    const int warp_n = wid >> 2;
    const int group = lane >> 2;
    const int kq = lane & 3;

    float acc[2][8][4];
#pragma unroll
    for (int mt = 0; mt < 2; mt++)
#pragma unroll
        for (int nt = 0; nt < 8; nt++)
#pragma unroll
            for (int c = 0; c < 4; c++) acc[mt][nt][c] = 0.f;

    const int nk = K >> 5;

#pragma unroll
    for (int t = 0; t < 4; t++) {
        int idx = tid + t * 256;
        int row = idx >> 3;
        int c4  = (idx & 7) << 2;
        cpa16(smA + row * LDS_S + c4, Ab + (size_t)row * K + c4);
        cpa16(smB + row * LDS_S + c4, Bp + (size_t)row * K + c4);
    }
    asm volatile("cp.async.commit_group;" ::: "memory");

    for (int kc = 0; kc < nk; kc++) {
        asm volatile("cp.async.wait_group 0;" ::: "memory");
        __syncthreads();

        if (kc + 1 < nk) {
            float* dA = smA + ((kc + 1) & 1) * STG;
            float* dB = smB + ((kc + 1) & 1) * STG;
            const int koff = (kc + 1) << 5;
#pragma unroll
            for (int t = 0; t < 4; t++) {
                int idx = tid + t * 256;
                int row = idx >> 3;
                int c4  = (idx & 7) << 2;
                cpa16(dA + row * LDS_S + c4, Ab + (size_t)row * K + koff + c4);
                cpa16(dB + row * LDS_S + c4, Bp + (size_t)row * K + koff + c4);
            }
            asm volatile("cp.async.commit_group;" ::: "memory");
        }

        const float* As = smA + (kc & 1) * STG;
        const float* Bs = smB + (kc & 1) * STG;

        // permuted layout: thread (group,kq) fragments for ks = 2h+kl live at
        // [row][kq*8 + 4h + 2kl .. +1]  -> float4 per (row, h)
#pragma unroll
        for (int h = 0; h < 2; h++) {
            uint4 a4[2][2];
#pragma unroll
            for (int mt = 0; mt < 2; mt++) {
                const float* ar = As + (warp_m * 32 + mt * 16 + group) * LDS_S + kq * 8 + h * 4;
                a4[mt][0] = *(const uint4*)ar;
                a4[mt][1] = *(const uint4*)(ar + 8 * LDS_S);
            }
            uint4 b4[8];
#pragma unroll
            for (int nt = 0; nt < 8; nt++)
                b4[nt] = *(const uint4*)(Bs + (warp_n * 64 + nt * 8 + group) * LDS_S + kq * 8 + h * 4);

            // kl = 0: components x,y ; kl = 1: components z,w
            {
                uint32_t af[2][4], bf[8][2];
#pragma unroll
                for (int mt = 0; mt < 2; mt++) {
                    af[mt][0] = a4[mt][0].x; af[mt][1] = a4[mt][1].x;
                    af[mt][2] = a4[mt][0].y; af[mt][3] = a4[mt][1].y;
                }
#pragma unroll
                for (int nt = 0; nt < 8; nt++) { bf[nt][0] = b4[nt].x; bf[nt][1] = b4[nt].y; }
#pragma unroll
                for (int mt = 0; mt < 2; mt++)
#pragma unroll
                    for (int nt = 0; nt < 8; nt++)
                        mma_tf32(acc[mt][nt], af[mt], bf[nt]);
            }
            {
                uint32_t af[2][4], bf[8][2];
#pragma unroll
                for (int mt = 0; mt < 2; mt++) {
                    af[mt][0] = a4[mt][0].z; af[mt][1] = a4[mt][1].z;
                    af[mt][2] = a4[mt][0].w; af[mt][3] = a4[mt][1].w;
                }
#pragma unroll
                for (int nt = 0; nt < 8; nt++) { bf[nt][0] = b4[nt].z; bf[nt][1] = b4[nt].w; }
#pragma unroll
                for (int mt = 0; mt < 2; mt++)
#pragma unroll
                    for (int nt = 0; nt < 8; nt++)
                        mma_tf32(acc[mt][nt], af[mt], bf[nt]);
            }
        }
    }

#pragma unroll
    for (int mt = 0; mt < 2; mt++) {
        int r = warp_m * 32 + mt * 16 + group;
#pragma unroll
        for (int nt = 0; nt < 8; nt++) {
            int cn = warp_n * 64 + nt * 8 + 2 * kq;
            *(float2*)(Crow0 + (size_t)r * N + cn) =
                make_float2(acc[mt][nt][0], acc[mt][nt][1]);
            *(float2*)(Crow0 + (size_t)(r + 8) * N + cn) =
                make_float2(acc[mt][nt][2], acc[mt][nt][3]);
        }
    }
}

// Merged QKV projection: grid.x 0..7 -> Q, 8..9 -> K, 10..11 -> V
__global__ __launch_bounds__(256, 2) void gemm_qkv(
    float* __restrict__ Qo, float* __restrict__ Ko, float* __restrict__ Vo)
{
    extern __shared__ float sm[];
    const int bx = blockIdx.x;
    const float* Bp;
    float* Cp;
    int N, nb;
    if (bx < 8)       { Bp = g_Wqr; Cp = Qo; N = QDIM;  nb = bx; }
    else if (bx < 10) { Bp = g_Wkr; Cp = Ko; N = KVDIM; nb = bx - 8; }
    else              { Bp = g_Wvr; Cp = Vo; N = KVDIM; nb = bx - 10; }
    gemm_body(g_Xr + (size_t)blockIdx.y * 128 * Cc,
              Bp + (size_t)nb * 128 * Cc,
              Cp + (size_t)blockIdx.y * 128 * N + nb * 128, N, Cc, sm);
}

__global__ __launch_bounds__(256, 2) void gemm_tc(
    const float* __restrict__ A, const float* __restrict__ B,
    float* __restrict__ C, int N, int K)
{
    extern __shared__ float sm[];
    gemm_body(A + (size_t)blockIdx.y * 128 * K,
              B + (size_t)blockIdx.x * 128 * K,
              C + (size_t)blockIdx.y * 128 * N + blockIdx.x * 128, N, K, sm);
}

// ---------------------------------------------------------------------------
// Postproc: per-token gate+V update, RoPE + RMS-norm on Q and K.
// ---------------------------------------------------------------------------
__global__ __launch_bounds__(256) void postproc(
    const float* __restrict__ x, const float* __restrict__ ve,
    const float* __restrict__ cosb, const float* __restrict__ sinb,
    const float* __restrict__ Wg)
{
    const int row = blockIdx.x;
    const int t = row & (Tt - 1);
    const int warp = threadIdx.x >> 5;
    const int lane = threadIdx.x & 31;

    if (warp < HKV) {
        float p = 0.f;
        if (lane < GATE_CH)
            p = x[(size_t)row * Cc + lane] * Wg[warp * GATE_CH + lane];
#pragma unroll
        for (int o = 16; o > 0; o >>= 1)
            p += __shfl_xor_sync(0xffffffffu, p, o);
        float gate = 3.f / (1.f + __expf(-p));
        size_t base = (size_t)row * KVDIM + warp * Dd;
        g_V[base + lane]      += gate * ve[base + lane];
        g_V[base + 32 + lane] += gate * ve[base + 32 + lane];
    }

    const float cv = cosb[t * 32 + lane];
    const float sv = sinb[t * 32 + lane];
    for (int tsk = warp; tsk < Hh + HKV; tsk += 8) {
        float* ptr = (tsk < Hh)
            ? (g_Q + (size_t)row * QDIM + tsk * Dd)
            : (g_K + (size_t)row * KVDIM + (tsk - Hh) * Dd);
        float x1 = ptr[lane];
        float x2 = ptr[lane + 32];
        float y1 = x1 * cv + x2 * sv;
        float y2 = x2 * cv - x1 * sv;
        float ss = y1 * y1 + y2 * y2;
#pragma unroll
        for (int o = 16; o > 0; o >>= 1)
            ss += __shfl_xor_sync(0xffffffffu, ss, o);
        float sc = 1.2f * rsqrtf(ss * (1.0f / Dd) + 1.1920929e-7f);
        ptr[lane]      = y1 * sc;
        ptr[lane + 32] = y2 * sc;
    }
}

// ---------------------------------------------------------------------------
// mma.sync flash attention. CTA = (qtile64, kv-head g, batch b), covering all
// 4 GQA q-heads: M=256 score rows. Epilogue stores tf32-rounded, k-PERMUTED Y.
// ---------------------------------------------------------------------------
#define SST 68   // smem row stride (floats)

__global__ __launch_bounds__(256, 1) void attn_mma(const int* __restrict__ wptr)
{
    extern __shared__ float dsm[];
    float* Ss = dsm;                        // [256][SST]
    float* Ks = dsm + 256 * SST;            // [64][SST]
    float* Vs = Ks + 64 * SST;              // [64][SST]

    const int qt = blockIdx.x, g = blockIdx.y, b = blockIdx.z;
    const int tid = threadIdx.x;
    const int wid = tid >> 5;
    const int lane = tid & 31;
    const int group = lane >> 2;
    const int kq = lane & 3;
    const int rbase = wid * 32;
    const int head = g * 4 + (wid >> 1);
    const int q0 = qt * 64;
    const int qloc0 = (wid & 1) * 32;

    uint32_t qf[2][8][4];
    {
        const float* Qb = g_Q + ((size_t)(b * Tt + q0)) * QDIM + head * Dd;
#pragma unroll
        for (int mt = 0; mt < 2; mt++) {
            int r0 = qloc0 + mt * 16 + group;
#pragma unroll
            for (int ks = 0; ks < 8; ks++) {
                int k0 = ks * 8 + kq;
                qf[mt][ks][0] = __float_as_uint(tf32r(Qb[(size_t)r0 * QDIM + k0]));
                qf[mt][ks][1] = __float_as_uint(tf32r(Qb[(size_t)(r0 + 8) * QDIM + k0]));
                qf[mt][ks][2] = __float_as_uint(tf32r(Qb[(size_t)r0 * QDIM + k0 + 4]));
                qf[mt][ks][3] = __float_as_uint(tf32r(Qb[(size_t)(r0 + 8) * QDIM + k0 + 4]));
            }
        }
    }

    float oacc[2][8][4];
#pragma unroll
    for (int mt = 0; mt < 2; mt++)
#pragma unroll
        for (int nt = 0; nt < 8; nt++)
#pragma unroll
            for (int c = 0; c < 4; c++) oacc[mt][nt][c] = 0.f;

    float mrow[2][2] = {{-1e30f, -1e30f}, {-1e30f, -1e30f}};
    float lrow[2][2] = {{0.f, 0.f}, {0.f, 0.f}};

    const int w = wptr[0];
    int jmin = q0 - w; if (jmin < 0) jmin = 0;

    for (int c0 = (jmin >> 6) << 6; c0 <= q0; c0 += 64) {
#pragma unroll
        for (int t = 0; t < 4; t++) {
            int idx = tid + t * 256;
            int key = idx >> 4;
            int d4  = (idx & 15) << 2;
            size_t src = ((size_t)(b * Tt + c0 + key)) * KVDIM + g * Dd + d4;
            float4 kv = *(const float4*)&g_K[src];
            float4 vv = *(const float4*)&g_V[src];
            float* kd = &Ks[key * SST + d4];
            kd[0] = tf32r(kv.x); kd[1] = tf32r(kv.y);
            kd[2] = tf32r(kv.z); kd[3] = tf32r(kv.w);
            float* vd = &Vs[key * SST + d4];
            vd[0] = tf32r(vv.x); vd[1] = tf32r(vv.y);
            vd[2] = tf32r(vv.z); vd[3] = tf32r(vv.w);
        }
        __syncthreads();

        float sacc[2][8][4];
#pragma unroll
        for (int mt = 0; mt < 2; mt++)
#pragma unroll
            for (int nt = 0; nt < 8; nt++)
#pragma unroll
                for (int c = 0; c < 4; c++) sacc[mt][nt][c] = 0.f;

#pragma unroll
        for (int ks = 0; ks < 8; ks++) {
            const int k0 = ks * 8;
            uint32_t bf[8][2];
#pragma unroll
            for (int nt = 0; nt < 8; nt++) {
                bf[nt][0] = __float_as_uint(Ks[(nt * 8 + group) * SST + k0 + kq]);
                bf[nt][1] = __float_as_uint(Ks[(nt * 8 + group) * SST + k0 + kq + 4]);
            }
#pragma unroll
            for (int mt = 0; mt < 2; mt++)
#pragma unroll
                for (int nt = 0; nt < 8; nt++)
                    mma_tf32(sacc[mt][nt], qf[mt][ks], bf[nt]);
        }

#pragma unroll
        for (int mt = 0; mt < 2; mt++) {
            const int i0 = q0 + qloc0 + mt * 16 + group;
            const int i1 = i0 + 8;
            float cmax0 = -1e30f, cmax1 = -1e30f;
#pragma unroll
            for (int nt = 0; nt < 8; nt++) {
                int jg = c0 + nt * 8 + 2 * kq;
                float s;
                s = (jg     <= i0 && (i0 - jg)     <= w) ? sacc[mt][nt][0] * 0.125f : -1e30f;
                sacc[mt][nt][0] = s; cmax0 = fmaxf(cmax0, s);
                s = (jg + 1 <= i0 && (i0 - jg - 1) <= w) ? sacc[mt][nt][1] * 0.125f : -1e30f;
                sacc[mt][nt][1] = s; cmax0 = fmaxf(cmax0, s);
                s = (jg     <= i1 && (i1 - jg)     <= w) ? sacc[mt][nt][2] * 0.125f : -1e30f;
                sacc[mt][nt][2] = s; cmax1 = fmaxf(cmax1, s);
                s = (jg + 1 <= i1 && (i1 - jg - 1) <= w) ? sacc[mt][nt][3] * 0.125f : -1e30f;
                sacc[mt][nt][3] = s; cmax1 = fmaxf(cmax1, s);
            }
            cmax0 = fmaxf(cmax0, __shfl_xor_sync(0xffffffffu, cmax0, 1));
            cmax0 = fmaxf(cmax0, __shfl_xor_sync(0xffffffffu, cmax0, 2));
            cmax1 = fmaxf(cmax1, __shfl_xor_sync(0xffffffffu, cmax1, 1));
            cmax1 = fmaxf(cmax1, __shfl_xor_sync(0xffffffffu, cmax1, 2));

            float mn0 = fmaxf(mrow[mt][0], cmax0);
            float mn1 = fmaxf(mrow[mt][1], cmax1);
            float r0 = __expf(mrow[mt][0] - mn0);
            float r1 = __expf(mrow[mt][1] - mn1);
            mrow[mt][0] = mn0; mrow[mt][1] = mn1;
            lrow[mt][0] *= r0; lrow[mt][1] *= r1;
#pragma unroll
            for (int nt = 0; nt < 8; nt++) {
                oacc[mt][nt][0] *= r0; oacc[mt][nt][1] *= r0;
                oacc[mt][nt][2] *= r1; oacc[mt][nt][3] *= r1;
            }
            const int prow0 = rbase + mt * 16 + group;
#pragma unroll
            for (int nt = 0; nt < 8; nt++) {
                float p0 = tf32r(__expf(sacc[mt][nt][0] - mn0));
                float p1 = tf32r(__expf(sacc[mt][nt][1] - mn0));
                float p2 = tf32r(__expf(sacc[mt][nt][2] - mn1));
                float p3 = tf32r(__expf(sacc[mt][nt][3] - mn1));
                lrow[mt][0] += p0 + p1;
                lrow[mt][1] += p2 + p3;
                *(float2*)&Ss[prow0 * SST + nt * 8 + 2 * kq] = make_float2(p0, p1);
                *(float2*)&Ss[(prow0 + 8) * SST + nt * 8 + 2 * kq] = make_float2(p2, p3);
            }
        }
        __syncwarp();

#pragma unroll
        for (int ks = 0; ks < 8; ks++) {
            const int k0 = ks * 8;
            uint32_t vf[8][2];
#pragma unroll
            for (int nt = 0; nt < 8; nt++) {
                vf[nt][0] = __float_as_uint(Vs[(k0 + kq) * SST + nt * 8 + group]);
                vf[nt][1] = __float_as_uint(Vs[(k0 + kq + 4) * SST + nt * 8 + group]);
            }
            uint32_t af[2][4];
#pragma unroll
            for (int mt = 0; mt < 2; mt++) {
                const int pr = rbase + mt * 16 + group;
                af[mt][0] = __float_as_uint(Ss[pr * SST + k0 + kq]);
                af[mt][1] = __float_as_uint(Ss[(pr + 8) * SST + k0 + kq]);
                af[mt][2] = __float_as_uint(Ss[pr * SST + k0 + kq + 4]);
                af[mt][3] = __float_as_uint(Ss[(pr + 8) * SST + k0 + kq + 4]);
            }
#pragma unroll
            for (int mt = 0; mt < 2; mt++)
#pragma unroll
                for (int nt = 0; nt < 8; nt++)
                    mma_tf32(oacc[mt][nt], af[mt], vf[nt]);
        }
        __syncthreads();
    }

    // finalize: store tf32-rounded Y in k-PERMUTED layout for the final GEMM
#pragma unroll
    for (int mt = 0; mt < 2; mt++) {
        float l0 = lrow[mt][0], l1 = lrow[mt][1];
        l0 += __shfl_xor_sync(0xffffffffu, l0, 1);
        l0 += __shfl_xor_sync(0xffffffffu, l0, 2);
        l1 += __shfl_xor_sync(0xffffffffu, l1, 1);
        l1 += __shfl_xor_sync(0xffffffffu, l1, 2);
        float inv0 = 1.f / l0, inv1 = 1.f / l1;
        int r0 = q0 + qloc0 + mt * 16 + group;
        float* Y0 = g_Y + ((size_t)(b * Tt + r0)) * QDIM + head * Dd;
        float* Y1 = g_Y + ((size_t)(b * Tt + r0 + 8)) * QDIM + head * Dd;
#pragma unroll
        for (int nt = 0; nt < 8; nt++) {
            int cn = nt * 8 + 2 * kq;
            int pA = (cn & ~31) + permc(cn & 31);
            int pB = (cn & ~31) + permc((cn + 1) & 31);
            Y0[pA] = tf32r(oacc[mt][nt][0] * inv0);
            Y0[pB] = tf32r(oacc[mt][nt][1] * inv0);
            Y1[pA] = tf32r(oacc[mt][nt][2] * inv1);
            Y1[pB] = tf32r(oacc[mt][nt][3] * inv1);
        }
    }
}

// ---------------------------------------------------------------------------
extern "C" void kernel_launch(void* const* d_in, const int* in_sizes, int n_in,
                              void* d_out, int out_size)
{
    const float* x    = (const float*)d_in[0];
    const float* ve   = (const float*)d_in[1];
    const float* cosb = (const float*)d_in[2];
    const float* sinb = (const float*)d_in[3];
    const float* Wq   = (const float*)d_in[4];
    const float* Wk   = (const float*)d_in[5];
    const float* Wv   = (const float*)d_in[6];
    const float* Wo   = (const float*)d_in[7];
    const float* Wg   = (const float*)d_in[8];
    const int*   win  = (const int*)d_in[9];

    float* out = (float*)d_out;

    float* Qp; cudaGetSymbolAddress((void**)&Qp, g_Q);
    float* Kp; cudaGetSymbolAddress((void**)&Kp, g_K);
    float* Vp; cudaGetSymbolAddress((void**)&Vp, g_V);
    float* Yp; cudaGetSymbolAddress((void**)&Yp, g_Y);
    float* Wor; cudaGetSymbolAddress((void**)&Wor, g_Wor);

    const int GEMM_SMEM = 4 * STG * 4;   // 73728 bytes
    cudaFuncSetAttribute(gemm_qkv,
        cudaFuncAttributeMaxDynamicSharedMemorySize, GEMM_SMEM);
    cudaFuncSetAttribute(gemm_tc,
        cudaFuncAttributeMaxDynamicSharedMemorySize, GEMM_SMEM);
    cudaFuncSetAttribute(attn_mma,
        cudaFuncAttributeMaxDynamicSharedMemorySize, (256 + 128) * SST * 4);

    // pre-round + k-permute x and weights
    round_pass<<<(RND_TOTAL4 + 255) / 256, 256>>>(x, Wq, Wk, Wv, Wo);

    // merged QKV projections (tf32 mma.sync)
    gemm_qkv<<<dim3(12, ROWS / 128), 256, GEMM_SMEM>>>(Qp, Kp, Vp);

    // gate + RoPE + RMS-norm
    postproc<<<ROWS, 256>>>(x, ve, cosb, sinb, Wg);

    // mma flash attention
    attn_mma<<<dim3(Tt / 64, HKV, Bb), 256, (256 + 128) * SST * 4>>>(win);

    // output projection
    gemm_tc<<<dim3(QDIM / 128, ROWS / 128), 256, GEMM_SMEM>>>(Yp, Wor, out, QDIM, Cc);
}

// round 12
// speedup vs baseline: 1.0920x; 1.0920x over previous
#include <cuda_runtime.h>
#include <cuda_bf16.h>
#include <math.h>
#include <cstdint>

// Problem constants
#define Bb 4
#define Tt 1024
#define Cc 1024
#define Hh 16
#define HKV 4
#define Dd 64
#define ROWS (Bb*Tt)          // 4096 tokens
#define QDIM (Hh*Dd)          // 1024
#define KVDIM (HKV*Dd)        // 256
#define GATE_CH 12

#define XN  (ROWS * Cc)
#define WQN (QDIM * Cc)
#define WKN (KVDIM * Cc)
#define WON (Cc * Cc)

// Scratch (no cudaMalloc allowed)
__device__ float g_Q[ROWS * QDIM];    // 16 MB
__device__ float g_K[ROWS * KVDIM];   // 4 MB
__device__ float g_V[ROWS * KVDIM];   // 4 MB
__device__ float g_Y[ROWS * QDIM];    // 16 MB
__device__ float g_Xr[XN];            // 16 MB  tf32-rounded x
__device__ float g_Wqr[WQN];          // 4 MB
__device__ float g_Wkr[WKN];          // 1 MB
__device__ float g_Wvr[WKN];          // 1 MB
__device__ float g_Wor[WON];          // 4 MB

__device__ __forceinline__ float tf32r(float x) {
    float y;
    asm("cvt.rna.tf32.f32 %0, %1;" : "=f"(y) : "f"(x));
    return y;
}

__device__ __forceinline__ void mma_tf32(float* d,
                                         const uint32_t* a, const uint32_t* b) {
    asm volatile(
        "mma.sync.aligned.m16n8k8.row.col.f32.tf32.tf32.f32 "
        "{%0,%1,%2,%3}, {%4,%5,%6,%7}, {%8,%9}, {%0,%1,%2,%3};"
        : "+f"(d[0]), "+f"(d[1]), "+f"(d[2]), "+f"(d[3])
        : "r"(a[0]), "r"(a[1]), "r"(a[2]), "r"(a[3]),
          "r"(b[0]), "r"(b[1]));
}

__device__ __forceinline__ void cpa16(float* s, const float* g) {
    uint32_t sa = (uint32_t)__cvta_generic_to_shared(s);
    asm volatile("cp.async.cg.shared.global [%0], [%1], 16;"
                 :: "r"(sa), "l"(g) : "memory");
}

// ---------------------------------------------------------------------------
// Pre-round pass: tf32-round x and all GEMM weights once (contiguous copies).
// ---------------------------------------------------------------------------
#define RND_TOTAL4 ((XN + WQN + 2 * WKN + WON) / 4)

__global__ __launch_bounds__(256) void round_pass(
    const float* __restrict__ x,
    const float* __restrict__ Wq, const float* __restrict__ Wk,
    const float* __restrict__ Wv, const float* __restrict__ Wo)
{
    int id = blockIdx.x * 256 + threadIdx.x;
    if (id >= RND_TOTAL4) return;
    int e = id * 4;
    const float* src;
    float* dst;
    if (e < XN)                { src = x  + e;         dst = g_Xr  + e; }
    else if ((e -= XN) < WQN)  { src = Wq + e;         dst = g_Wqr + e; }
    else if ((e -= WQN) < WKN) { src = Wk + e;         dst = g_Wkr + e; }
    else if ((e -= WKN) < WKN) { src = Wv + e;         dst = g_Wvr + e; }
    else                       { src = Wo + (e - WKN); dst = g_Wor + (e - WKN); }
    float4 v = *(const float4*)src;
    v.x = tf32r(v.x); v.y = tf32r(v.y); v.z = tf32r(v.z); v.w = tf32r(v.w);
    *(float4*)dst = v;
}

// ---------------------------------------------------------------------------
// tf32 mma.sync GEMM core (R7 layout):  C_tile = A[128,K] * B[128,K]^T
// ---------------------------------------------------------------------------
#define LDS_S 36
#define STG (128 * LDS_S)

__device__ __forceinline__ void gemm_body(
    const float* __restrict__ Ab, const float* __restrict__ Bp,
    float* __restrict__ Crow0, int N, int K, float* __restrict__ sm)
{
    float* smA = sm;
    float* smB = sm + 2 * STG;

    const int tid = threadIdx.x;
    const int wid = tid >> 5;
    const int lane = tid & 31;
    const int warp_m = wid & 3;
    const int warp_n = wid >> 2;
    const int group = lane >> 2;
    const int kq = lane & 3;

    float acc[2][8][4];
#pragma unroll
    for (int mt = 0; mt < 2; mt++)
#pragma unroll
        for (int nt = 0; nt < 8; nt++)
#pragma unroll
            for (int c = 0; c < 4; c++) acc[mt][nt][c] = 0.f;

    const int nk = K >> 5;

#pragma unroll
    for (int t = 0; t < 4; t++) {
        int idx = tid + t * 256;
        int row = idx >> 3;
        int c4  = (idx & 7) << 2;
        cpa16(smA + row * LDS_S + c4, Ab + (size_t)row * K + c4);
        cpa16(smB + row * LDS_S + c4, Bp + (size_t)row * K + c4);
    }
    asm volatile("cp.async.commit_group;" ::: "memory");

    for (int kc = 0; kc < nk; kc++) {
        asm volatile("cp.async.wait_group 0;" ::: "memory");
        __syncthreads();

        if (kc + 1 < nk) {
            float* dA = smA + ((kc + 1) & 1) * STG;
            float* dB = smB + ((kc + 1) & 1) * STG;
            const int koff = (kc + 1) << 5;
#pragma unroll
            for (int t = 0; t < 4; t++) {
                int idx = tid + t * 256;
                int row = idx >> 3;
                int c4  = (idx & 7) << 2;
                cpa16(dA + row * LDS_S + c4, Ab + (size_t)row * K + koff + c4);
                cpa16(dB + row * LDS_S + c4, Bp + (size_t)row * K + koff + c4);
            }
            asm volatile("cp.async.commit_group;" ::: "memory");
        }

        const uint32_t* As = (const uint32_t*)(smA + (kc & 1) * STG);
        const uint32_t* Bs = (const uint32_t*)(smB + (kc & 1) * STG);
#pragma unroll
        for (int ks = 0; ks < 4; ks++) {
            const int k0 = ks * 8;
            uint32_t af[2][4];
#pragma unroll
            for (int mt = 0; mt < 2; mt++) {
                const uint32_t* ar = As + (warp_m * 32 + mt * 16 + group) * LDS_S + k0 + kq;
                af[mt][0] = ar[0];
                af[mt][1] = ar[8 * LDS_S];
                af[mt][2] = ar[4];
                af[mt][3] = ar[8 * LDS_S + 4];
            }
            uint32_t bf[8][2];
#pragma unroll
            for (int nt = 0; nt < 8; nt++) {
                const uint32_t* br = Bs + (warp_n * 64 + nt * 8 + group) * LDS_S + k0 + kq;
                bf[nt][0] = br[0];
                bf[nt][1] = br[4];
            }
#pragma unroll
            for (int mt = 0; mt < 2; mt++)
#pragma unroll
                for (int nt = 0; nt < 8; nt++)
                    mma_tf32(acc[mt][nt], af[mt], bf[nt]);
        }
    }

#pragma unroll
    for (int mt = 0; mt < 2; mt++) {
        int r = warp_m * 32 + mt * 16 + group;
#pragma unroll
        for (int nt = 0; nt < 8; nt++) {
            int cn = warp_n * 64 + nt * 8 + 2 * kq;
            *(float2*)(Crow0 + (size_t)r * N + cn) =
                make_float2(acc[mt][nt][0], acc[mt][nt][1]);
            *(float2*)(Crow0 + (size_t)(r + 8) * N + cn) =
                make_float2(acc[mt][nt][2], acc[mt][nt][3]);
        }
    }
}

// Merged QKV projection: grid.x 0..7 -> Q, 8..9 -> K, 10..11 -> V
__global__ __launch_bounds__(256, 2) void gemm_qkv(
    float* __restrict__ Qo, float* __restrict__ Ko, float* __restrict__ Vo)
{
    extern __shared__ float sm[];
    const int bx = blockIdx.x;
    const float* Bp;
    float* Cp;
    int N, nb;
    if (bx < 8)       { Bp = g_Wqr; Cp = Qo; N = QDIM;  nb = bx; }
    else if (bx < 10) { Bp = g_Wkr; Cp = Ko; N = KVDIM; nb = bx - 8; }
    else              { Bp = g_Wvr; Cp = Vo; N = KVDIM; nb = bx - 10; }
    gemm_body(g_Xr + (size_t)blockIdx.y * 128 * Cc,
              Bp + (size_t)nb * 128 * Cc,
              Cp + (size_t)blockIdx.y * 128 * N + nb * 128, N, Cc, sm);
}

__global__ __launch_bounds__(256, 2) void gemm_tc(
    const float* __restrict__ A, const float* __restrict__ B,
    float* __restrict__ C, int N, int K)
{
    extern __shared__ float sm[];
    gemm_body(A + (size_t)blockIdx.y * 128 * K,
              B + (size_t)blockIdx.x * 128 * K,
              C + (size_t)blockIdx.y * 128 * N + blockIdx.x * 128, N, K, sm);
}

// ---------------------------------------------------------------------------
// Postproc: per-token gate+V update, RoPE + RMS-norm on Q and K.
// ---------------------------------------------------------------------------
__global__ __launch_bounds__(256) void postproc(
    const float* __restrict__ x, const float* __restrict__ ve,
    const float* __restrict__ cosb, const float* __restrict__ sinb,
    const float* __restrict__ Wg)
{
    const int row = blockIdx.x;
    const int t = row & (Tt - 1);
    const int warp = threadIdx.x >> 5;
    const int lane = threadIdx.x & 31;

    if (warp < HKV) {
        float p = 0.f;
        if (lane < GATE_CH)
            p = x[(size_t)row * Cc + lane] * Wg[warp * GATE_CH + lane];
#pragma unroll
        for (int o = 16; o > 0; o >>= 1)
            p += __shfl_xor_sync(0xffffffffu, p, o);
        float gate = 3.f / (1.f + __expf(-p));
        size_t base = (size_t)row * KVDIM + warp * Dd;
        g_V[base + lane]      += gate * ve[base + lane];
        g_V[base + 32 + lane] += gate * ve[base + 32 + lane];
    }

    const float cv = cosb[t * 32 + lane];
    const float sv = sinb[t * 32 + lane];
    for (int tsk = warp; tsk < Hh + HKV; tsk += 8) {
        float* ptr = (tsk < Hh)
            ? (g_Q + (size_t)row * QDIM + tsk * Dd)
            : (g_K + (size_t)row * KVDIM + (tsk - Hh) * Dd);
        float x1 = ptr[lane];
        float x2 = ptr[lane + 32];
        float y1 = x1 * cv + x2 * sv;
        float y2 = x2 * cv - x1 * sv;
        float ss = y1 * y1 + y2 * y2;
#pragma unroll
        for (int o = 16; o > 0; o >>= 1)
            ss += __shfl_xor_sync(0xffffffffu, ss, o);
        float sc = 1.2f * rsqrtf(ss * (1.0f / Dd) + 1.1920929e-7f);
        ptr[lane]      = y1 * sc;
        ptr[lane + 32] = y2 * sc;
    }
}

// ---------------------------------------------------------------------------
// mma.sync flash attention, M=128 variant. CTA = (qtile32, kv-head g, batch b)
// covering all 4 GQA q-heads: 128 score rows (4 heads x 32 queries).
// 8 warps x 16 rows (mt=1): ~halved register state -> no spills, 2 CTAs/SM.
// ---------------------------------------------------------------------------
#define SST 68   // smem row stride (floats)
#define QT 32    // queries per CTA

__global__ __launch_bounds__(256, 2) void attn_mma(const int* __restrict__ wptr)
{
    extern __shared__ float dsm[];
    float* Ss = dsm;                        // [128][SST]
    float* Ks = dsm + 128 * SST;            // [64][SST]
    float* Vs = Ks + 64 * SST;              // [64][SST]

    const int qt = blockIdx.x, g = blockIdx.y, b = blockIdx.z;
    const int tid = threadIdx.x;
    const int wid = tid >> 5;
    const int lane = tid & 31;
    const int group = lane >> 2;
    const int kq = lane & 3;
    const int head = g * 4 + (wid >> 1);    // 2 warps per head
    const int q0 = qt * QT;
    const int qloc0 = (wid & 1) * 16;       // query offset within head (0 or 16)

    // Q fragments (registers), tf32-rounded: 16 rows x 64 dims
    uint32_t qf[8][4];
    {
        const float* Qb = g_Q + ((size_t)(b * Tt + q0 + qloc0)) * QDIM + head * Dd;
        int r0 = group;
#pragma unroll
        for (int ks = 0; ks < 8; ks++) {
            int k0 = ks * 8 + kq;
            qf[ks][0] = __float_as_uint(tf32r(Qb[(size_t)r0 * QDIM + k0]));
            qf[ks][1] = __float_as_uint(tf32r(Qb[(size_t)(r0 + 8) * QDIM + k0]));
            qf[ks][2] = __float_as_uint(tf32r(Qb[(size_t)r0 * QDIM + k0 + 4]));
            qf[ks][3] = __float_as_uint(tf32r(Qb[(size_t)(r0 + 8) * QDIM + k0 + 4]));
        }
    }

    float oacc[8][4];
#pragma unroll
    for (int nt = 0; nt < 8; nt++)
#pragma unroll
        for (int c = 0; c < 4; c++) oacc[nt][c] = 0.f;

    float m0 = -1e30f, m1 = -1e30f, l0 = 0.f, l1 = 0.f;

    const int w = wptr[0];
    int jmin = q0 - w; if (jmin < 0) jmin = 0;

    for (int c0 = (jmin >> 6) << 6; c0 <= q0; c0 += 64) {
        // load K,V chunk (tf32-rounded at store)
#pragma unroll
        for (int t = 0; t < 4; t++) {
            int idx = tid + t * 256;
            int key = idx >> 4;
            int d4  = (idx & 15) << 2;
            size_t src = ((size_t)(b * Tt + c0 + key)) * KVDIM + g * Dd + d4;
            float4 kv = *(const float4*)&g_K[src];
            float4 vv = *(const float4*)&g_V[src];
            float* kd = &Ks[key * SST + d4];
            kd[0] = tf32r(kv.x); kd[1] = tf32r(kv.y);
            kd[2] = tf32r(kv.z); kd[3] = tf32r(kv.w);
            float* vd = &Vs[key * SST + d4];
            vd[0] = tf32r(vv.x); vd[1] = tf32r(vv.y);
            vd[2] = tf32r(vv.z); vd[3] = tf32r(vv.w);
        }
        __syncthreads();

        // scores: S = Q * K^T
        float sacc[8][4];
#pragma unroll
        for (int nt = 0; nt < 8; nt++)
#pragma unroll
            for (int c = 0; c < 4; c++) sacc[nt][c] = 0.f;

#pragma unroll
        for (int ks = 0; ks < 8; ks++) {
            const int k0 = ks * 8;
            uint32_t bf[8][2];
#pragma unroll
            for (int nt = 0; nt < 8; nt++) {
                bf[nt][0] = __float_as_uint(Ks[(nt * 8 + group) * SST + k0 + kq]);
                bf[nt][1] = __float_as_uint(Ks[(nt * 8 + group) * SST + k0 + kq + 4]);
            }
#pragma unroll
            for (int nt = 0; nt < 8; nt++)
                mma_tf32(sacc[nt], qf[ks], bf[nt]);
        }

        // mask + scale + online softmax
        {
            const int i0 = q0 + qloc0 + group;
            const int i1 = i0 + 8;
            float cmax0 = -1e30f, cmax1 = -1e30f;
#pragma unroll
            for (int nt = 0; nt < 8; nt++) {
                int jg = c0 + nt * 8 + 2 * kq;
                float s;
                s = (jg     <= i0 && (i0 - jg)     <= w) ? sacc[nt][0] * 0.125f : -1e30f;
                sacc[nt][0] = s; cmax0 = fmaxf(cmax0, s);
                s = (jg + 1 <= i0 && (i0 - jg - 1) <= w) ? sacc[nt][1] * 0.125f : -1e30f;
                sacc[nt][1] = s; cmax0 = fmaxf(cmax0, s);
                s = (jg     <= i1 && (i1 - jg)     <= w) ? sacc[nt][2] * 0.125f : -1e30f;
                sacc[nt][2] = s; cmax1 = fmaxf(cmax1, s);
                s = (jg + 1 <= i1 && (i1 - jg - 1) <= w) ? sacc[nt][3] * 0.125f : -1e30f;
                sacc[nt][3] = s; cmax1 = fmaxf(cmax1, s);
            }
            cmax0 = fmaxf(cmax0, __shfl_xor_sync(0xffffffffu, cmax0, 1));
            cmax0 = fmaxf(cmax0, __shfl_xor_sync(0xffffffffu, cmax0, 2));
            cmax1 = fmaxf(cmax1, __shfl_xor_sync(0xffffffffu, cmax1, 1));
            cmax1 = fmaxf(cmax1, __shfl_xor_sync(0xffffffffu, cmax1, 2));

            float mn0 = fmaxf(m0, cmax0);
            float mn1 = fmaxf(m1, cmax1);
            float r0 = __expf(m0 - mn0);
            float r1 = __expf(m1 - mn1);
            m0 = mn0; m1 = mn1;
            l0 *= r0; l1 *= r1;
#pragma unroll
            for (int nt = 0; nt < 8; nt++) {
                oacc[nt][0] *= r0; oacc[nt][1] *= r0;
                oacc[nt][2] *= r1; oacc[nt][3] *= r1;
            }
            const int prow0 = wid * 16 + group;
#pragma unroll
            for (int nt = 0; nt < 8; nt++) {
                float p0 = tf32r(__expf(sacc[nt][0] - mn0));
                float p1 = tf32r(__expf(sacc[nt][1] - mn0));
                float p2 = tf32r(__expf(sacc[nt][2] - mn1));
                float p3 = tf32r(__expf(sacc[nt][3] - mn1));
                l0 += p0 + p1;
                l1 += p2 + p3;
                *(float2*)&Ss[prow0 * SST + nt * 8 + 2 * kq] = make_float2(p0, p1);
                *(float2*)&Ss[(prow0 + 8) * SST + nt * 8 + 2 * kq] = make_float2(p2, p3);
            }
        }
        __syncwarp();

        // PV: O += P * V
#pragma unroll
        for (int ks = 0; ks < 8; ks++) {
            const int k0 = ks * 8;
            uint32_t vf[8][2];
#pragma unroll
            for (int nt = 0; nt < 8; nt++) {
                vf[nt][0] = __float_as_uint(Vs[(k0 + kq) * SST + nt * 8 + group]);
                vf[nt][1] = __float_as_uint(Vs[(k0 + kq + 4) * SST + nt * 8 + group]);
            }
            uint32_t af[4];
            {
                const int pr = wid * 16 + group;
                af[0] = __float_as_uint(Ss[pr * SST + k0 + kq]);
                af[1] = __float_as_uint(Ss[(pr + 8) * SST + k0 + kq]);
                af[2] = __float_as_uint(Ss[pr * SST + k0 + kq + 4]);
                af[3] = __float_as_uint(Ss[(pr + 8) * SST + k0 + kq + 4]);
            }
#pragma unroll
            for (int nt = 0; nt < 8; nt++)
                mma_tf32(oacc[nt], af, vf[nt]);
        }
        __syncthreads();
    }

    // finalize: store tf32-rounded Y
    {
        l0 += __shfl_xor_sync(0xffffffffu, l0, 1);
        l0 += __shfl_xor_sync(0xffffffffu, l0, 2);
        l1 += __shfl_xor_sync(0xffffffffu, l1, 1);
        l1 += __shfl_xor_sync(0xffffffffu, l1, 2);
        float inv0 = 1.f / l0, inv1 = 1.f / l1;
        int r0 = q0 + qloc0 + group;
        float* Y0 = g_Y + ((size_t)(b * Tt + r0)) * QDIM + head * Dd;
        float* Y1 = g_Y + ((size_t)(b * Tt + r0 + 8)) * QDIM + head * Dd;
#pragma unroll
        for (int nt = 0; nt < 8; nt++) {
            int cn = nt * 8 + 2 * kq;
            *(float2*)(Y0 + cn) = make_float2(tf32r(oacc[nt][0] * inv0),
                                              tf32r(oacc[nt][1] * inv0));
            *(float2*)(Y1 + cn) = make_float2(tf32r(oacc[nt][2] * inv1),
                                              tf32r(oacc[nt][3] * inv1));
        }
    }
}

// ---------------------------------------------------------------------------
extern "C" void kernel_launch(void* const* d_in, const int* in_sizes, int n_in,
                              void* d_out, int out_size)
{
    const float* x    = (const float*)d_in[0];
    const float* ve   = (const float*)d_in[1];
    const float* cosb = (const float*)d_in[2];
    const float* sinb = (const float*)d_in[3];
    const float* Wq   = (const float*)d_in[4];
    const float* Wk   = (const float*)d_in[5];
    const float* Wv   = (const float*)d_in[6];
    const float* Wo   = (const float*)d_in[7];
    const float* Wg   = (const float*)d_in[8];
    const int*   win  = (const int*)d_in[9];

    float* out = (float*)d_out;

    float* Qp; cudaGetSymbolAddress((void**)&Qp, g_Q);
    float* Kp; cudaGetSymbolAddress((void**)&Kp, g_K);
    float* Vp; cudaGetSymbolAddress((void**)&Vp, g_V);
    float* Yp; cudaGetSymbolAddress((void**)&Yp, g_Y);
    float* Wor; cudaGetSymbolAddress((void**)&Wor, g_Wor);

    const int GEMM_SMEM = 4 * STG * 4;            // 73728 bytes
    const int ATTN_SMEM = (128 + 128) * SST * 4;  // 69632 bytes
    cudaFuncSetAttribute(gemm_qkv,
        cudaFuncAttributeMaxDynamicSharedMemorySize, GEMM_SMEM);
    cudaFuncSetAttribute(gemm_tc,
        cudaFuncAttributeMaxDynamicSharedMemorySize, GEMM_SMEM);
    cudaFuncSetAttribute(attn_mma,
        cudaFuncAttributeMaxDynamicSharedMemorySize, ATTN_SMEM);

    // pre-round x and weights to tf32
    round_pass<<<(RND_TOTAL4 + 255) / 256, 256>>>(x, Wq, Wk, Wv, Wo);

    // merged QKV projections (tf32 mma.sync)
    gemm_qkv<<<dim3(12, ROWS / 128), 256, GEMM_SMEM>>>(Qp, Kp, Vp);

    // gate + RoPE + RMS-norm
    postproc<<<ROWS, 256>>>(x, ve, cosb, sinb, Wg);

    // mma flash attention (M=128 tiles, 2 CTAs/SM)
    attn_mma<<<dim3(Tt / QT, HKV, Bb), 256, ATTN_SMEM>>>(win);

    // output projection
    gemm_tc<<<dim3(QDIM / 128, ROWS / 128), 256, GEMM_SMEM>>>(Yp, Wor, out, QDIM, Cc);
}